// round 1
// baseline (speedup 1.0000x reference)
#include <cuda_runtime.h>
#include <cuda_bf16.h>
#include <cstdint>

// ---------------------------------------------------------------------------
// InfoNCE loss (gradcache): N=16384, D=128, t=0.07
// loss = mean_i [ log( sum_j exp(q.d_j/t) + sum_{j!=i} exp(q.q_j/t) ) - q_i.d_i/t ]
// ---------------------------------------------------------------------------

#define NROWS 16384
#define DIM   128
#define D4    (DIM/4)          // 32 float4 per row
#define BM    64
#define BN    64
#define ROWTILES (NROWS/BM)    // 256
#define CHUNKS   8             // 4 chunks over d-matrix cols, 4 over q-matrix cols
#define TILES_PER_CHUNK (NROWS/4/BN)   // 64
#define PAD_F4   33            // row stride in float4 for smem tiles
#define SMEM_F4  (2*BM*PAD_F4)
#define SMEM_BYTES (SMEM_F4*16)

// inv_t and inv_t*log2(e)
#define INV_T    14.285714285714286f
#define SCALE_L2 20.609929155556620f   // (1/0.07)*log2(e)

// scratch (device globals: no allocation allowed)
__device__ float g_qn[NROWS*DIM];
__device__ float g_dn[NROWS*DIM];
__device__ float g_parts[CHUNKS][NROWS];   // disjoint row-sum slices
__device__ float g_partial[64];

// fast exp2 with degree-5 polynomial (rel err ~2e-6), pure FMA/ALU pipe (no MUFU)
__device__ __forceinline__ float fast_exp2(float x) {
    float nf = rintf(x);
    float r  = x - nf;                     // r in [-0.5, 0.5]
    float p  = 0.0013333558f;
    p = fmaf(p, r, 0.0096181298f);
    p = fmaf(p, r, 0.0555041087f);
    p = fmaf(p, r, 0.2402265070f);
    p = fmaf(p, r, 0.6931471806f);
    p = fmaf(p, r, 1.0f);
    int n = (int)nf;
    float s = __int_as_float((n + 127) << 23);   // 2^n (|n| <= ~30 here)
    return p * s;
}

// ---------------------------------------------------------------------------
// Kernel 1: L2-normalize rows of q and d. One warp per row.
// grid: 4096 blocks x 256 threads (8 warps); 32768 rows total (q then d).
// ---------------------------------------------------------------------------
__global__ void k_normalize(const float* __restrict__ q, const float* __restrict__ d) {
    int warp = (blockIdx.x * (blockDim.x >> 5)) + (threadIdx.x >> 5);
    int lane = threadIdx.x & 31;
    const float* src;
    float* dst;
    int row;
    if (warp < NROWS) { src = q; dst = g_qn; row = warp; }
    else              { src = d; dst = g_dn; row = warp - NROWS; }
    const float4* s4 = reinterpret_cast<const float4*>(src) + row * D4;
    float4* d4 = reinterpret_cast<float4*>(dst) + row * D4;
    float4 v = s4[lane];
    float ss = v.x*v.x + v.y*v.y + v.z*v.z + v.w*v.w;
    #pragma unroll
    for (int off = 16; off; off >>= 1)
        ss += __shfl_xor_sync(0xffffffffu, ss, off);
    float r = rsqrtf(ss);
    v.x *= r; v.y *= r; v.z *= r; v.w *= r;
    d4[lane] = v;
}

// ---------------------------------------------------------------------------
// Kernel 2: main fused GEMM + exp + row-sum.
// grid (ROWTILES, CHUNKS), 256 threads. Block computes, for its 64 q-rows,
// the partial row-sum over 4096 columns of either d-hat (chunk<4) or q-hat.
// Thread layout: tr = tid/16 (row group), tc = tid%16 (col lane).
// Thread owns rows tr*4+u (u<4) and cols v*16+tc (v<4).
// ---------------------------------------------------------------------------
__global__ void __launch_bounds__(256)
k_main() {
    extern __shared__ float4 smem[];
    float4* As4 = smem;                 // [BM][PAD_F4]
    float4* Bs4 = smem + BM * PAD_F4;   // [BN][PAD_F4]

    const int t  = threadIdx.x;
    const int tr = t >> 4;
    const int tc = t & 15;
    const int rowBase = blockIdx.x * BM;
    const int chunk   = blockIdx.y;
    const bool isQ    = (chunk >= 4);
    const int colBase0 = (chunk & 3) * (NROWS / 4);
    const float4* colSrc = reinterpret_cast<const float4*>(isQ ? g_qn : g_dn);
    const float4* qsrc   = reinterpret_cast<const float4*>(g_qn);

    // load A tile (64 x 128) once
    #pragma unroll
    for (int i = 0; i < 8; i++) {
        int f   = t + 256 * i;          // 0..2047
        int row = f >> 5;
        int kq  = f & 31;
        As4[row * PAD_F4 + kq] = qsrc[(rowBase + row) * D4 + kq];
    }

    float rowsum[4] = {0.f, 0.f, 0.f, 0.f};

    for (int ct = 0; ct < TILES_PER_CHUNK; ct++) {
        int colBase = colBase0 + ct * BN;
        __syncthreads();   // previous tile's compute done (and A load on iter 0)
        #pragma unroll
        for (int i = 0; i < 8; i++) {
            int f   = t + 256 * i;
            int row = f >> 5;
            int kq  = f & 31;
            Bs4[row * PAD_F4 + kq] = colSrc[(colBase + row) * D4 + kq];
        }
        __syncthreads();

        float acc[4][4];
        #pragma unroll
        for (int u = 0; u < 4; u++)
            #pragma unroll
            for (int v = 0; v < 4; v++)
                acc[u][v] = 0.f;

        #pragma unroll 4
        for (int k4 = 0; k4 < 32; k4++) {
            float4 av[4], bv[4];
            #pragma unroll
            for (int u = 0; u < 4; u++) av[u] = As4[(tr * 4 + u) * PAD_F4 + k4];
            #pragma unroll
            for (int v = 0; v < 4; v++) bv[v] = Bs4[(v * 16 + tc) * PAD_F4 + k4];
            #pragma unroll
            for (int u = 0; u < 4; u++)
                #pragma unroll
                for (int v = 0; v < 4; v++) {
                    acc[u][v] = fmaf(av[u].x, bv[v].x, acc[u][v]);
                    acc[u][v] = fmaf(av[u].y, bv[v].y, acc[u][v]);
                    acc[u][v] = fmaf(av[u].z, bv[v].z, acc[u][v]);
                    acc[u][v] = fmaf(av[u].w, bv[v].w, acc[u][v]);
                }
        }

        // fused epilogue: exp(dot/t) = exp2(dot * SCALE_L2); skip qq diagonal
        #pragma unroll
        for (int u = 0; u < 4; u++) {
            int grow = rowBase + tr * 4 + u;
            #pragma unroll
            for (int v = 0; v < 4; v++) {
                int gcol = colBase + v * 16 + tc;
                float e = fast_exp2(acc[u][v] * SCALE_L2);
                if (!(isQ && gcol == grow)) rowsum[u] += e;
            }
        }
    }

    // reduce across the 16 column-lanes sharing each row (lane halves of a warp)
    #pragma unroll
    for (int u = 0; u < 4; u++) {
        float s = rowsum[u];
        #pragma unroll
        for (int off = 8; off; off >>= 1)
            s += __shfl_down_sync(0xffffffffu, s, off, 16);
        if (tc == 0) g_parts[chunk][rowBase + tr * 4 + u] = s;
    }
}

// ---------------------------------------------------------------------------
// Kernel 3: per-row term = log(sim_v) - dot(qn,dn)*inv_t; block partial sums.
// 64 blocks x 256 threads (8 warps); warp per row, 32 rows per warp.
// ---------------------------------------------------------------------------
__global__ void k_finalize() {
    int lane = threadIdx.x & 31;
    int warpInBlock = threadIdx.x >> 5;
    int gwarp = blockIdx.x * 8 + warpInBlock;
    const float4* q4 = reinterpret_cast<const float4*>(g_qn);
    const float4* d4 = reinterpret_cast<const float4*>(g_dn);

    float acc = 0.f;
    for (int r = 0; r < 32; r++) {
        int row = gwarp + r * 512;
        float4 a = q4[row * D4 + lane];
        float4 b = d4[row * D4 + lane];
        float p = a.x*b.x + a.y*b.y + a.z*b.z + a.w*b.w;
        #pragma unroll
        for (int off = 16; off; off >>= 1)
            p += __shfl_xor_sync(0xffffffffu, p, off);
        if (lane == 0) {
            float sv = 0.f;
            #pragma unroll
            for (int c = 0; c < CHUNKS; c++) sv += g_parts[c][row];
            acc += logf(sv) - p * INV_T;
        }
    }
    __shared__ float ws[8];
    if (lane == 0) ws[warpInBlock] = acc;
    __syncthreads();
    if (threadIdx.x == 0) {
        float s = 0.f;
        #pragma unroll
        for (int w = 0; w < 8; w++) s += ws[w];
        g_partial[blockIdx.x] = s;
    }
}

// ---------------------------------------------------------------------------
// Kernel 4: final scalar reduce
// ---------------------------------------------------------------------------
__global__ void k_reduce(float* out) {
    __shared__ float sh[64];
    sh[threadIdx.x] = g_partial[threadIdx.x];
    __syncthreads();
    if (threadIdx.x == 0) {
        float s = 0.f;
        #pragma unroll
        for (int i = 0; i < 64; i++) s += sh[i];
        out[0] = s * (1.0f / NROWS);
    }
}

extern "C" void kernel_launch(void* const* d_in, const int* in_sizes, int n_in,
                              void* d_out, int out_size) {
    const float* q = (const float*)d_in[0];
    const float* d = (const float*)d_in[1];
    float* out = (float*)d_out;

    cudaFuncSetAttribute(k_main, cudaFuncAttributeMaxDynamicSharedMemorySize, SMEM_BYTES);

    k_normalize<<<(2 * NROWS) / 8, 256>>>(q, d);
    k_main<<<dim3(ROWTILES, CHUNKS), 256, SMEM_BYTES>>>();
    k_finalize<<<64, 256>>>();
    k_reduce<<<1, 64>>>(out);
}

// round 4
// speedup vs baseline: 5.6634x; 5.6634x over previous
#include <cuda_runtime.h>
#include <cuda_bf16.h>
#include <cstdint>

// ---------------------------------------------------------------------------
// InfoNCE loss (gradcache): N=16384, D=128, t=0.07
// HMMA (mma.sync bf16) version — tcgen05 unavailable (ptxas target sm_100).
// loss = mean_i [ log( sum_j exp(q.d_j/t) + sum_{j!=i} exp(q.q_j/t) ) - q_i.d_i/t ]
// ---------------------------------------------------------------------------

#define NROWS 16384
#define DIM   128
#define D4    32
#define BM    128           // CTA row tile
#define BN    64            // column tile per iteration
#define NTILES 512          // 32768 columns / 64
#define KSTEPS 8            // 128 / 16
#define INV_T    14.285714285714286f
#define SCALE_L2 20.609929155556620f   // (1/0.07)*log2(e)

#define SMA_BYTES 32768     // A: 128 rows x 256 B
#define SMB_BYTES 16384     // B: 64 rows x 256 B
#define SMEM_TOTAL (SMA_BYTES + 2*SMB_BYTES)

// device scratch (no allocation allowed)
__device__ float g_qn[NROWS*DIM];
__device__ float g_dn[NROWS*DIM];
__device__ __nv_bfloat16 g_qb[NROWS*DIM];
__device__ __nv_bfloat16 g_db[NROWS*DIM];
__device__ float g_parts[2][NROWS];
__device__ float g_partial[64];

__device__ __forceinline__ uint32_t smem_u32(const void* p) {
    uint32_t a;
    asm("{ .reg .u64 t; cvta.to.shared.u64 t, %1; cvt.u32.u64 %0, t; }" : "=r"(a) : "l"(p));
    return a;
}

#define LDMATRIX_X4(r, addr) \
    asm volatile("ldmatrix.sync.aligned.m8n8.x4.shared.b16 {%0,%1,%2,%3}, [%4];" \
        : "=r"((r)[0]), "=r"((r)[1]), "=r"((r)[2]), "=r"((r)[3]) : "r"(addr))

#define MMA_16816(c, a, b0, b1) \
    asm volatile("mma.sync.aligned.m16n8k16.row.col.f32.bf16.bf16.f32 " \
        "{%0,%1,%2,%3}, {%4,%5,%6,%7}, {%8,%9}, {%0,%1,%2,%3};" \
        : "+f"((c)[0]), "+f"((c)[1]), "+f"((c)[2]), "+f"((c)[3]) \
        : "r"((a)[0]), "r"((a)[1]), "r"((a)[2]), "r"((a)[3]), "r"(b0), "r"(b1))

#define CP_ASYNC16(dst, src) \
    asm volatile("cp.async.cg.shared.global [%0], [%1], 16;" :: "r"(dst), "l"(src))
#define CP_COMMIT() asm volatile("cp.async.commit_group;" ::: "memory")
#define CP_WAIT(n)  asm volatile("cp.async.wait_group %0;" :: "n"(n) : "memory")

// swizzled byte offset within a 256B-row tile: unit u (16B) of row
__device__ __forceinline__ uint32_t swz(int row, int u) {
    return (uint32_t)(row * 256 + ((u ^ (row & 7)) << 4));
}

__device__ __forceinline__ float ex2f(float x) {
    float e; asm("ex2.approx.f32 %0, %1;" : "=f"(e) : "f"(x)); return e;
}

// ---------------------------------------------------------------------------
// Kernel 1: L2-normalize rows of q and d; write fp32 (numerator) + bf16 (MMA)
// ---------------------------------------------------------------------------
__global__ void k_normalize(const float* __restrict__ q, const float* __restrict__ d) {
    int warp = (blockIdx.x * (blockDim.x >> 5)) + (threadIdx.x >> 5);
    int lane = threadIdx.x & 31;
    const float* src; float* dstf; __nv_bfloat162* dstb; int row;
    if (warp < NROWS) { src = q; dstf = g_qn; dstb = reinterpret_cast<__nv_bfloat162*>(g_qb); row = warp; }
    else              { src = d; dstf = g_dn; dstb = reinterpret_cast<__nv_bfloat162*>(g_db); row = warp - NROWS; }
    const float4* s4 = reinterpret_cast<const float4*>(src) + row * D4;
    float4* d4 = reinterpret_cast<float4*>(dstf) + row * D4;
    float4 v = s4[lane];
    float ss = v.x*v.x + v.y*v.y + v.z*v.z + v.w*v.w;
    #pragma unroll
    for (int off = 16; off; off >>= 1) ss += __shfl_xor_sync(0xffffffffu, ss, off);
    float r = rsqrtf(ss);
    v.x *= r; v.y *= r; v.z *= r; v.w *= r;
    d4[lane] = v;
    dstb[row * 64 + lane * 2 + 0] = __float22bfloat162_rn(make_float2(v.x, v.y));
    dstb[row * 64 + lane * 2 + 1] = __float22bfloat162_rn(make_float2(v.z, v.w));
}

// ---------------------------------------------------------------------------
// Kernel 2: HMMA main loop. 128 CTAs x 256 threads (8 warps, 4M x 2N layout).
// Warp tile 32x32. A-fragments register-resident; B double-buffered cp.async.
// ---------------------------------------------------------------------------
__global__ void __launch_bounds__(256, 1) k_main() {
    extern __shared__ char smem[];
    const int tid = threadIdx.x;
    const int w = tid >> 5, lane = tid & 31;
    const int bx = (int)blockIdx.x;
    const uint32_t smA = smem_u32(smem);
    const uint32_t smB0 = smA + SMA_BYTES;

    // ---- stage A tile (this CTA's 128 q-rows) into swizzled smem ----
    {
        const uint4* ga = reinterpret_cast<const uint4*>(g_qb) + (size_t)bx * BM * 16;
        int row = tid >> 1, ub = (tid & 1) * 8;
        #pragma unroll
        for (int j = 0; j < 8; j++) {
            int u = ub + j;
            *reinterpret_cast<uint4*>(smem + swz(row, u)) = ga[row * 16 + u];
        }
    }

    // ---- prefetch B tile 0 ----
    {
        const uint4* gs = reinterpret_cast<const uint4*>(g_db);
        int row = tid >> 2, ub = (tid & 3) * 4;
        #pragma unroll
        for (int j = 0; j < 4; j++) {
            int u = ub + j;
            CP_ASYNC16(smB0 + swz(row, u), gs + row * 16 + u);
        }
        CP_COMMIT();
    }
    __syncthreads();

    // ---- load A fragments into registers (held across all 512 tiles) ----
    uint32_t afr[KSTEPS][2][4];
    const int mw = (w >> 1) * 32;
    #pragma unroll
    for (int ks = 0; ks < KSTEPS; ks++) {
        #pragma unroll
        for (int mf = 0; mf < 2; mf++) {
            int row = mw + mf * 16 + (lane & 15);
            int unit = 2 * ks + (lane >> 4);
            uint32_t addr = smA + swz(row, unit);
            LDMATRIX_X4(afr[ks][mf], addr);
        }
    }

    const int nw = (w & 1) * 32;
    float rs[4] = {0.f, 0.f, 0.f, 0.f};

    for (int ct = 0; ct < NTILES; ct++) {
        // prefetch tile ct+1 into the other buffer
        if (ct + 1 < NTILES) {
            int nt = ct + 1;
            const uint4* gs = (nt < 256)
                ? (reinterpret_cast<const uint4*>(g_db) + (size_t)nt * BN * 16)
                : (reinterpret_cast<const uint4*>(g_qb) + (size_t)(nt - 256) * BN * 16);
            uint32_t dstb = smB0 + ((nt & 1) ? SMB_BYTES : 0);
            int row = tid >> 2, ub = (tid & 3) * 4;
            #pragma unroll
            for (int j = 0; j < 4; j++) {
                int u = ub + j;
                CP_ASYNC16(dstb + swz(row, u), gs + row * 16 + u);
            }
            CP_COMMIT();
            CP_WAIT(1);     // tile ct's group complete (in-order)
        } else {
            CP_WAIT(0);
        }
        __syncthreads();

        const uint32_t smB = smB0 + ((ct & 1) ? SMB_BYTES : 0);

        float acc[2][4][4];
        #pragma unroll
        for (int mf = 0; mf < 2; mf++)
            #pragma unroll
            for (int n8 = 0; n8 < 4; n8++)
                #pragma unroll
                for (int r = 0; r < 4; r++) acc[mf][n8][r] = 0.f;

        #pragma unroll
        for (int ks = 0; ks < KSTEPS; ks++) {
            uint32_t bfr[2][4];
            #pragma unroll
            for (int g = 0; g < 2; g++) {
                int row = nw + g * 16 + (lane & 7) + ((lane >> 4) << 3);
                int unit = 2 * ks + ((lane >> 3) & 1);
                LDMATRIX_X4(bfr[g], smB + swz(row, unit));
            }
            #pragma unroll
            for (int mf = 0; mf < 2; mf++)
                #pragma unroll
                for (int n8 = 0; n8 < 4; n8++)
                    MMA_16816(acc[mf][n8], afr[ks][mf],
                              bfr[n8 >> 1][(n8 & 1) * 2], bfr[n8 >> 1][(n8 & 1) * 2 + 1]);
        }

        // fused epilogue: exp(dot/t) = exp2(dot*SCALE_L2), row-sum; skip qq diag
        const bool diag = (ct >= 256) && (((ct - 256) >> 1) == bx);
        if (!diag) {
            #pragma unroll
            for (int mf = 0; mf < 2; mf++)
                #pragma unroll
                for (int n8 = 0; n8 < 4; n8++) {
                    float e0 = ex2f(acc[mf][n8][0] * SCALE_L2);
                    float e1 = ex2f(acc[mf][n8][1] * SCALE_L2);
                    float e2 = ex2f(acc[mf][n8][2] * SCALE_L2);
                    float e3 = ex2f(acc[mf][n8][3] * SCALE_L2);
                    rs[mf * 2 + 0] += e0 + e1;
                    rs[mf * 2 + 1] += e2 + e3;
                }
        } else {
            const int colbase = (ct - 256) * BN;
            #pragma unroll
            for (int mf = 0; mf < 2; mf++) {
                int grow_lo = bx * BM + mw + mf * 16 + (lane >> 2);
                int grow_hi = grow_lo + 8;
                #pragma unroll
                for (int n8 = 0; n8 < 4; n8++) {
                    int gc0 = colbase + nw + n8 * 8 + ((lane & 3) << 1);
                    int gc1 = gc0 + 1;
                    float e0 = (gc0 == grow_lo) ? 0.f : ex2f(acc[mf][n8][0] * SCALE_L2);
                    float e1 = (gc1 == grow_lo) ? 0.f : ex2f(acc[mf][n8][1] * SCALE_L2);
                    float e2 = (gc0 == grow_hi) ? 0.f : ex2f(acc[mf][n8][2] * SCALE_L2);
                    float e3 = (gc1 == grow_hi) ? 0.f : ex2f(acc[mf][n8][3] * SCALE_L2);
                    rs[mf * 2 + 0] += e0 + e1;
                    rs[mf * 2 + 1] += e2 + e3;
                }
            }
        }
        __syncthreads();   // all warps done with smB before it is overwritten
    }

    // reduce the 4 lanes sharing each row (lanes differ only in n-columns)
    #pragma unroll
    for (int j = 0; j < 4; j++) {
        float s = rs[j];
        s += __shfl_xor_sync(0xffffffffu, s, 1);
        s += __shfl_xor_sync(0xffffffffu, s, 2);
        if ((lane & 3) == 0) {
            int row = bx * BM + mw + (j >> 1) * 16 + (j & 1) * 8 + (lane >> 2);
            g_parts[w & 1][row] = s;
        }
    }
}

// ---------------------------------------------------------------------------
// Kernel 3: per-row term = log(sim_v) - dot(qn,dn)/t; block partial sums.
// ---------------------------------------------------------------------------
__global__ void k_finalize() {
    int lane = threadIdx.x & 31;
    int warpInBlock = threadIdx.x >> 5;
    int gwarp = blockIdx.x * 8 + warpInBlock;
    const float4* q4 = reinterpret_cast<const float4*>(g_qn);
    const float4* d4 = reinterpret_cast<const float4*>(g_dn);

    float acc = 0.f;
    for (int r = 0; r < 32; r++) {
        int row = gwarp + r * 512;
        float4 a = q4[row * D4 + lane];
        float4 b = d4[row * D4 + lane];
        float p = a.x*b.x + a.y*b.y + a.z*b.z + a.w*b.w;
        #pragma unroll
        for (int off = 16; off; off >>= 1) p += __shfl_xor_sync(0xffffffffu, p, off);
        if (lane == 0) {
            float sv = g_parts[0][row] + g_parts[1][row];
            acc += logf(sv) - p * INV_T;
        }
    }
    __shared__ float ws[8];
    if (lane == 0) ws[warpInBlock] = acc;
    __syncthreads();
    if (threadIdx.x == 0) {
        float s = 0.f;
        #pragma unroll
        for (int w = 0; w < 8; w++) s += ws[w];
        g_partial[blockIdx.x] = s;
    }
}

__global__ void k_reduce(float* out) {
    __shared__ float sh[64];
    sh[threadIdx.x] = g_partial[threadIdx.x];
    __syncthreads();
    if (threadIdx.x == 0) {
        float s = 0.f;
        #pragma unroll
        for (int i = 0; i < 64; i++) s += sh[i];
        out[0] = s * (1.0f / NROWS);
    }
}

extern "C" void kernel_launch(void* const* d_in, const int* in_sizes, int n_in,
                              void* d_out, int out_size) {
    const float* q = (const float*)d_in[0];
    const float* d = (const float*)d_in[1];
    float* out = (float*)d_out;

    cudaFuncSetAttribute(k_main, cudaFuncAttributeMaxDynamicSharedMemorySize, SMEM_TOTAL);

    k_normalize<<<(2 * NROWS) / 8, 256>>>(q, d);
    k_main<<<128, 256, SMEM_TOTAL>>>();
    k_finalize<<<64, 256>>>();
    k_reduce<<<1, 64>>>(out);
}